// round 2
// baseline (speedup 1.0000x reference)
#include <cuda_runtime.h>
#include <math.h>

#define NB  16
#define C   256
#define H   80
#define W   80
#define MIP 8
#define L   160            // H + W
#define BN_EPS 1e-5f

// Scratch (device globals: no allocations allowed in kernel_launch)
__device__ float g_y [NB * C * L];   // concatenated means:  [n][c][l], l<80: x_h (row means), l>=80: x_w (col means)
__device__ float g_ah[NB * C * H];   // a_h attention map
__device__ float g_aw[NB * C * W];   // a_w attention map

// ---------------------------------------------------------------------------
// Kernel 1: per-(n,c) plane row means (over w) and column means (over h).
// One block per plane. Plane staged in smem with row stride 81 (81 mod 32 = 17,
// gcd(17,32)=1) so both the column reduction (stride-1 across threads) and the
// row reduction (stride-81 across threads) are bank-conflict-free.
// ---------------------------------------------------------------------------
__global__ __launch_bounds__(256) void k1_means(const float* __restrict__ x) {
    __shared__ float tile[H * (W + 1)];
    const int plane = blockIdx.x;                 // n*C + c
    const float4* xp = (const float4*)(x + (size_t)plane * (H * W));

    // Load 80x80 plane (1600 float4) into padded smem
    for (int i = threadIdx.x; i < (H * W) / 4; i += 256) {
        float4 v = xp[i];
        int e = i * 4;
        int r = e / W;
        int j = e - r * W;
        float* t = &tile[r * (W + 1) + j];
        t[0] = v.x; t[1] = v.y; t[2] = v.z; t[3] = v.w;
    }
    __syncthreads();

    const float inv80 = 1.0f / 80.0f;
    const int tid = threadIdx.x;
    if (tid < W) {
        // column means  -> x_w  (mean over h), stored at l in [80,160)
        float s = 0.f;
        #pragma unroll 8
        for (int r = 0; r < H; r++) s += tile[r * (W + 1) + tid];
        g_y[plane * L + H + tid] = s * inv80;
    } else if (tid >= 128 && tid < 128 + H) {
        // row means -> x_h (mean over w), stored at l in [0,80)
        int r = tid - 128;
        float s = 0.f;
        #pragma unroll 8
        for (int j = 0; j < W; j++) s += tile[r * (W + 1) + j];
        g_y[plane * L + r] = s * inv80;
    }
}

// ---------------------------------------------------------------------------
// Kernel 2: per-batch bottleneck.
//   y2[m,l] = sum_c w_fc[m,c] * g_y[n,c,l]           (8 x 160, K=256)
//   y2 = BN(y2); y2 = y2*sigmoid(y2)                 (swish) -> smem
//   a_h[c,l] = sigmoid(sum_m w_h[c,m]*y2[m,l])       l in [0,80)
//   a_w[c,l] = sigmoid(sum_m w_w[c,m]*y2[m,80+l])
// One block per n (16 blocks, 256 threads).
// ---------------------------------------------------------------------------
__device__ __forceinline__ float fsig(float v) {
    return 1.f / (1.f + __expf(-v));
}

__global__ __launch_bounds__(256) void k2_attn(const float* __restrict__ w_fc,
                                               const float* __restrict__ bn_gamma,
                                               const float* __restrict__ bn_beta,
                                               const float* __restrict__ bn_mean,
                                               const float* __restrict__ bn_var,
                                               const float* __restrict__ w_h,
                                               const float* __restrict__ w_w) {
    __shared__ float ys[MIP * L];                 // swished bottleneck, 5 KB
    const int n = blockIdx.x;
    const int tid = threadIdx.x;
    const float* __restrict__ yb = g_y + (size_t)n * C * L;

    // GEMM1 + BN + swish: 1280 outputs, 5 per thread
    #pragma unroll
    for (int k = 0; k < 5; k++) {
        int o = tid + k * 256;                    // o in [0,1280)
        int m = o / L;
        int l = o - m * L;
        float acc = 0.f;
        #pragma unroll 8
        for (int c = 0; c < C; c++)
            acc = fmaf(w_fc[m * C + c], yb[c * L + l], acc);
        float inv  = bn_gamma[m] * rsqrtf(bn_var[m] + BN_EPS);
        float v    = acc * inv + (bn_beta[m] - bn_mean[m] * inv);
        ys[o] = v * fsig(v);
    }
    __syncthreads();

    // GEMM2 + sigmoid: thread t owns channel c = t
    const int c = tid;
    float wh[MIP], ww[MIP];
    #pragma unroll
    for (int m = 0; m < MIP; m++) {
        wh[m] = w_h[c * MIP + m];
        ww[m] = w_w[c * MIP + m];
    }
    float* __restrict__ ahp = g_ah + ((size_t)n * C + c) * H;
    float* __restrict__ awp = g_aw + ((size_t)n * C + c) * W;
    #pragma unroll 4
    for (int l = 0; l < H; l++) {
        float sh = 0.f, sw = 0.f;
        #pragma unroll
        for (int m = 0; m < MIP; m++) {
            sh = fmaf(wh[m], ys[m * L + l],     sh);
            sw = fmaf(ww[m], ys[m * L + H + l], sw);
        }
        ahp[l] = fsig(sh);
        awp[l] = fsig(sw);
    }
}

// ---------------------------------------------------------------------------
// Kernel 3: out[n,c,h,w] = x * a_h[n,c,h] * a_w[n,c,w], one float4 per thread.
// ---------------------------------------------------------------------------
__global__ __launch_bounds__(256) void k3_apply(const float* __restrict__ x,
                                                float* __restrict__ out) {
    const int i = blockIdx.x * 256 + threadIdx.x;       // float4 index
    const int e = i * 4;                                // element index
    const int w0    = e % W;                            // 4-aligned (80 % 4 == 0)
    const int t     = e / W;
    const int hh    = t % H;
    const int plane = t / H;                            // n*C + c

    const float  ah  = g_ah[plane * H + hh];
    const float4 aw4 = *(const float4*)(g_aw + plane * W + w0);
    const float4 xv  = ((const float4*)x)[i];

    float4 r;
    r.x = xv.x * (ah * aw4.x);
    r.y = xv.y * (ah * aw4.y);
    r.z = xv.z * (ah * aw4.z);
    r.w = xv.w * (ah * aw4.w);
    ((float4*)out)[i] = r;
}

// ---------------------------------------------------------------------------
extern "C" void kernel_launch(void* const* d_in, const int* in_sizes, int n_in,
                              void* d_out, int out_size) {
    const float* x        = (const float*)d_in[0];
    const float* w_fc     = (const float*)d_in[1];
    const float* bn_gamma = (const float*)d_in[2];
    const float* bn_beta  = (const float*)d_in[3];
    const float* bn_mean  = (const float*)d_in[4];
    const float* bn_var   = (const float*)d_in[5];
    const float* w_h      = (const float*)d_in[6];
    const float* w_w      = (const float*)d_in[7];
    float* out = (float*)d_out;

    k1_means<<<NB * C, 256>>>(x);
    k2_attn<<<NB, 256>>>(w_fc, bn_gamma, bn_beta, bn_mean, bn_var, w_h, w_w);
    const int n4 = NB * C * H * W / 4;          // 6,553,600 float4
    k3_apply<<<n4 / 256, 256>>>(x, out);
}

// round 3
// speedup vs baseline: 1.8564x; 1.8564x over previous
#include <cuda_runtime.h>
#include <math.h>

#define NB  16
#define C   256
#define H   80
#define W   80
#define MIP 8
#define L   160            // H + W
#define BN_EPS 1e-5f

// Scratch (device globals: no allocations allowed)
__device__ float g_y [NB * C * L];   // [n][c][l]: l<80 row means (x_h), l>=80 col means (x_w)
__device__ float g_ah[NB * C * H];
__device__ float g_aw[NB * C * W];

__device__ __forceinline__ float fsig(float v) { return 1.f / (1.f + __expf(-v)); }

// ---------------------------------------------------------------------------
// k1: one block (320 thr) per 80x80 plane. 20 column-groups x 16 row-groups.
// Column partials accumulate in registers; only tiny partials go through smem.
// ---------------------------------------------------------------------------
__global__ __launch_bounds__(320) void k1_means(const float* __restrict__ x) {
    __shared__ float s_row[H][21];     // horizontal (4-wide) sums per (row, q);  21: gcd(21,32)=1
    __shared__ float s_col[W][17];     // column partials per (col, rowgroup);    17: gcd(17,32)=1
    const int plane = blockIdx.x;
    const int t  = threadIdx.x;
    const int q  = t % 20;             // float4 column group: cols 4q..4q+3
    const int rg = t / 20;             // row group 0..15
    const float4* __restrict__ xp = (const float4*)(x + (size_t)plane * (H * W));

    float4 cacc = make_float4(0.f, 0.f, 0.f, 0.f);
    #pragma unroll
    for (int i = 0; i < 5; i++) {
        int r = i * 16 + rg;
        float4 v = xp[r * 20 + q];
        cacc.x += v.x; cacc.y += v.y; cacc.z += v.z; cacc.w += v.w;
        s_row[r][q] = v.x + v.y + v.z + v.w;
    }
    s_col[4 * q + 0][rg] = cacc.x;
    s_col[4 * q + 1][rg] = cacc.y;
    s_col[4 * q + 2][rg] = cacc.z;
    s_col[4 * q + 3][rg] = cacc.w;
    __syncthreads();

    const float inv80 = 1.0f / 80.0f;
    if (t < H) {
        // row mean (over w) -> x_h at l = t
        float s = 0.f;
        #pragma unroll
        for (int j = 0; j < 20; j++) s += s_row[t][j];
        g_y[(size_t)plane * L + t] = s * inv80;
    } else if (t >= 160 && t < 160 + W) {
        // column mean (over h) -> x_w at l = 80 + col
        int col = t - 160;
        float s = 0.f;
        #pragma unroll
        for (int g = 0; g < 16; g++) s += s_col[col][g];
        g_y[(size_t)plane * L + H + col] = s * inv80;
    }
}

// ---------------------------------------------------------------------------
// k2: grid (16, 2), block 320. GEMM1 coalesced over l; GEMM2 register-hoisted.
// ---------------------------------------------------------------------------
__global__ __launch_bounds__(320) void k2_attn(const float* __restrict__ w_fc,
                                               const float* __restrict__ bn_gamma,
                                               const float* __restrict__ bn_beta,
                                               const float* __restrict__ bn_mean,
                                               const float* __restrict__ bn_var,
                                               const float* __restrict__ w_h,
                                               const float* __restrict__ w_w) {
    __shared__ float ys[MIP * L];        // swished bottleneck (5 KB)
    __shared__ float wfcT[C * MIP];      // w_fc transposed (8 KB)
    const int n = blockIdx.x;
    const int t = threadIdx.x;

    if (t < C) {
        #pragma unroll
        for (int m = 0; m < MIP; m++) wfcT[t * MIP + m] = w_fc[m * C + t];
    }
    __syncthreads();

    const float* __restrict__ yb = g_y + (size_t)n * C * L;
    if (t < L) {
        float acc[MIP];
        #pragma unroll
        for (int m = 0; m < MIP; m++) acc[m] = 0.f;
        #pragma unroll 4
        for (int c = 0; c < C; c++) {
            float v = yb[c * L + t];                     // coalesced across threads
            const float4* wr = (const float4*)(wfcT + c * MIP);
            float4 a = wr[0], b = wr[1];
            acc[0] = fmaf(a.x, v, acc[0]); acc[1] = fmaf(a.y, v, acc[1]);
            acc[2] = fmaf(a.z, v, acc[2]); acc[3] = fmaf(a.w, v, acc[3]);
            acc[4] = fmaf(b.x, v, acc[4]); acc[5] = fmaf(b.y, v, acc[5]);
            acc[6] = fmaf(b.z, v, acc[6]); acc[7] = fmaf(b.w, v, acc[7]);
        }
        #pragma unroll
        for (int m = 0; m < MIP; m++) {
            float iv = bn_gamma[m] * rsqrtf(bn_var[m] + BN_EPS);
            float vv = acc[m] * iv + (bn_beta[m] - bn_mean[m] * iv);
            ys[m * L + t] = vv * fsig(vv);
        }
    }
    __syncthreads();

    // GEMM2 + sigmoid. thread -> (l = t%80, channel group), 32 channels each.
    const int l  = t % 80;
    const int cg = t / 80;                               // 0..3
    const int c0 = (blockIdx.y * 4 + cg) * 32;           // 8 groups x 32 = 256 channels
    float yh[MIP], yw[MIP];
    #pragma unroll
    for (int m = 0; m < MIP; m++) { yh[m] = ys[m * L + l]; yw[m] = ys[m * L + H + l]; }

    float* __restrict__ ahp = g_ah + (size_t)n * C * H;
    float* __restrict__ awp = g_aw + (size_t)n * C * W;
    #pragma unroll 4
    for (int c = c0; c < c0 + 32; c++) {
        const float4* wh4 = (const float4*)(w_h + c * MIP);
        const float4* ww4 = (const float4*)(w_w + c * MIP);
        float4 ha = wh4[0], hb = wh4[1];
        float4 wa = ww4[0], wb = ww4[1];
        float sh = 0.f, sw = 0.f;
        sh = fmaf(ha.x, yh[0], sh); sh = fmaf(ha.y, yh[1], sh);
        sh = fmaf(ha.z, yh[2], sh); sh = fmaf(ha.w, yh[3], sh);
        sh = fmaf(hb.x, yh[4], sh); sh = fmaf(hb.y, yh[5], sh);
        sh = fmaf(hb.z, yh[6], sh); sh = fmaf(hb.w, yh[7], sh);
        sw = fmaf(wa.x, yw[0], sw); sw = fmaf(wa.y, yw[1], sw);
        sw = fmaf(wa.z, yw[2], sw); sw = fmaf(wa.w, yw[3], sw);
        sw = fmaf(wb.x, yw[4], sw); sw = fmaf(wb.y, yw[5], sw);
        sw = fmaf(wb.z, yw[6], sw); sw = fmaf(wb.w, yw[7], sw);
        ahp[c * H + l] = fsig(sh);                       // coalesced across threads
        awp[c * W + l] = fsig(sw);
    }
}

// ---------------------------------------------------------------------------
// k3: grid (5, 4096), block 320 = 16 rows x 20 float4-cols of one plane slab.
// ---------------------------------------------------------------------------
__global__ __launch_bounds__(320) void k3_apply(const float* __restrict__ x,
                                                float* __restrict__ out) {
    const int plane = blockIdx.y;                        // n*C + c
    const int t  = threadIdx.x;
    const int q  = t % 20;
    const int hh = blockIdx.x * 16 + t / 20;

    const float  ah  = g_ah[(size_t)plane * H + hh];
    const float4 aw4 = ((const float4*)(g_aw + (size_t)plane * W))[q];

    const size_t i = (size_t)plane * (H * W / 4) + hh * 20 + q;
    const float4 xv = ((const float4*)x)[i];

    float4 r;
    r.x = xv.x * (ah * aw4.x);
    r.y = xv.y * (ah * aw4.y);
    r.z = xv.z * (ah * aw4.z);
    r.w = xv.w * (ah * aw4.w);
    ((float4*)out)[i] = r;
}

// ---------------------------------------------------------------------------
extern "C" void kernel_launch(void* const* d_in, const int* in_sizes, int n_in,
                              void* d_out, int out_size) {
    const float* x        = (const float*)d_in[0];
    const float* w_fc     = (const float*)d_in[1];
    const float* bn_gamma = (const float*)d_in[2];
    const float* bn_beta  = (const float*)d_in[3];
    const float* bn_mean  = (const float*)d_in[4];
    const float* bn_var   = (const float*)d_in[5];
    const float* w_h      = (const float*)d_in[6];
    const float* w_w      = (const float*)d_in[7];
    float* out = (float*)d_out;

    k1_means<<<NB * C, 320>>>(x);
    k2_attn<<<dim3(NB, 2), 320>>>(w_fc, bn_gamma, bn_beta, bn_mean, bn_var, w_h, w_w);
    k3_apply<<<dim3(5, NB * C), 320>>>(x, out);
}